// round 8
// baseline (speedup 1.0000x reference)
#include <cuda_runtime.h>
#include <cuda_bf16.h>
#include <cstdint>

#define B_    4096
#define FIN   64
#define NK    512
#define FOUT  256
#define TB    32
#define NTHR  512
#define AP    40            // A pitch in b32: conflict-free fragment reads

typedef unsigned long long ull;

__device__ float    g_cc[NK];
__device__ float    g_s2[NK];
__device__ uint32_t g_Wpk[131072];   // 512KB: B fragments in register order
                                     // u32 q: j'=q&3, lane=(q>>2)&31, half=(q>>7)&1,
                                     //        ks=(q>>8)&3, wn=(q>>10)&7, h=q>>13

// ---- smem (u32 offsets): only the shared rbf tile + reductions ----
#define SM_A    0               // [512 kp_eff][AP] : kp 0-255 = R_hi, 256-511 = R_lo
#define SM_PART 20480           // [16][32]
#define SM_INV  20992           // [32]
#define SM_TOT  21024
#define SMEM_BYTES (SM_TOT * 4) // ~84 KB

#define FMA2(a,b,c) asm("fma.rn.f32x2 %0, %1, %2, %0;" : "+l"(a) : "l"(b), "l"(c))
#define UNPK(lo,hi,v) asm("mov.b64 {%0,%1}, %2;" : "=f"(lo), "=f"(hi) : "l"(v))

__device__ __forceinline__ uint32_t pack_bf2(__nv_bfloat16 a, __nv_bfloat16 b) {
    __nv_bfloat162 t; t.x = a; t.y = b;
    return *reinterpret_cast<uint32_t*>(&t);
}

#define MMA16816(D,a0,a1,a2,a3,b0,b1) \
    asm("mma.sync.aligned.m16n8k16.row.col.f32.bf16.bf16.f32 " \
        "{%0,%1,%2,%3}, {%4,%5,%6,%7}, {%8,%9}, {%0,%1,%2,%3};" \
        : "+f"(D[0]), "+f"(D[1]), "+f"(D[2]), "+f"(D[3]) \
        : "r"(a0), "r"(a1), "r"(a2), "r"(a3), "r"(b0), "r"(b1))

// -------- prep: ||c||^2, exp(2 ls), W split-bf16 register-order pack --------
__global__ void prep_all(const float* __restrict__ W,
                         const float* __restrict__ centers,
                         const float* __restrict__ ls) {
    int bid = blockIdx.x;
    if (bid < 16) {
        int kb = bid * 32;
        int warp = threadIdx.x >> 5, lane = threadIdx.x & 31;
        #pragma unroll
        for (int c = warp; c < 32; c += 8) {
            int k = kb + c;
            float v0 = centers[k * FIN + lane];
            float v1 = centers[k * FIN + 32 + lane];
            float s = fmaf(v0, v0, v1 * v1);
            #pragma unroll
            for (int off = 16; off; off >>= 1) s += __shfl_xor_sync(0xffffffffu, s, off);
            if (lane == 0) g_cc[k] = s;
        }
        if (threadIdx.x < 32) g_s2[kb + threadIdx.x] = __expf(2.f * ls[kb + threadIdx.x]);
    } else {
        int q = (bid - 16) * 256 + threadIdx.x;      // 0..131071
        int jp   = q & 3;
        int lane = (q >> 2) & 31;
        int half = (q >> 7) & 1;
        int ks   = (q >> 8) & 3;
        int wn   = (q >> 10) & 7;
        int h    = q >> 13;                          // 0-7: W_hi, 8-15: W_lo
        int j    = half * 4 + jp;
        int t    = j >> 1;
        int ki   = j & 1;
        int g    = lane >> 2;
        int tig  = lane & 3;
        int col  = wn * 32 + t * 8 + g;
        int k    = (h & 7) * 64 + (ks * 8 + tig) * 2 + 8 * ki;
        float w0 = W[(size_t)col * NK + k];
        float w1 = W[(size_t)col * NK + k + 1];
        __nv_bfloat16 h0 = __float2bfloat16(w0);
        __nv_bfloat16 h1 = __float2bfloat16(w1);
        __nv_bfloat16 v0 = (h >= 8) ? __float2bfloat16(w0 - __bfloat162float(h0)) : h0;
        __nv_bfloat16 v1 = (h >= 8) ? __float2bfloat16(w1 - __bfloat162float(h1)) : h1;
        g_Wpk[q] = pack_bf2(v0, v1);
    }
}

// -------- fused main kernel --------
__global__ __launch_bounds__(NTHR, 1)
void rbf_main(const float* __restrict__ x,
              const float* __restrict__ centers,
              float* __restrict__ out) {
    extern __shared__ float sm[];
    uint32_t* A32 = (uint32_t*)sm + SM_A;
    const int tid  = threadIdx.x;
    const int lane = tid & 31;
    const int warp = tid >> 5;
    const int b0   = blockIdx.x * TB;

    // ---- hoist this lane's x row via direct LDG; xx in registers ----
    ull xr[32];
    {
        const ulonglong2* xrow = (const ulonglong2*)(x + (size_t)(b0 + lane) * FIN);
        #pragma unroll
        for (int f = 0; f < 16; f++) {
            ulonglong2 v = __ldg(xrow + f);
            xr[2 * f] = v.x; xr[2 * f + 1] = v.y;
        }
    }
    float xx;
    {
        ull s = 0;
        #pragma unroll
        for (int i = 0; i < 32; i++) FMA2(s, xr[i], xr[i]);
        float lo, hi; UNPK(lo, hi, s); xx = lo + hi;
    }

    // ---- phase 1: warp-autonomous, zero syncs. warp w owns centers [32w,32w+32) ----
    float psum = 0.f;
    for (int j = 0; j < 8; j++) {
        const int kg = warp * 32 + j * 4;
        const ulonglong2* cb = (const ulonglong2*)(centers + (size_t)kg * FIN);
        ull a0 = 0, a1 = 0, a2 = 0, a3 = 0;
        #pragma unroll
        for (int f = 0; f < 16; f++) {
            ulonglong2 c0 = __ldg(cb + f);
            ulonglong2 c1 = __ldg(cb + 16 + f);
            ulonglong2 c2 = __ldg(cb + 32 + f);
            ulonglong2 c3 = __ldg(cb + 48 + f);
            FMA2(a0, xr[2*f], c0.x); FMA2(a0, xr[2*f+1], c0.y);
            FMA2(a1, xr[2*f], c1.x); FMA2(a1, xr[2*f+1], c1.y);
            FMA2(a2, xr[2*f], c2.x); FMA2(a2, xr[2*f+1], c2.y);
            FMA2(a3, xr[2*f], c3.x); FMA2(a3, xr[2*f+1], c3.y);
        }
        float lo, hi, r2, v0, v1, v2, v3;
        UNPK(lo, hi, a0); r2 = fmaf(-2.f, lo + hi, xx + __ldg(g_cc + kg + 0));
        v0 = __expf(-__ldg(g_s2 + kg + 0) * r2);
        UNPK(lo, hi, a1); r2 = fmaf(-2.f, lo + hi, xx + __ldg(g_cc + kg + 1));
        v1 = __expf(-__ldg(g_s2 + kg + 1) * r2);
        UNPK(lo, hi, a2); r2 = fmaf(-2.f, lo + hi, xx + __ldg(g_cc + kg + 2));
        v2 = __expf(-__ldg(g_s2 + kg + 2) * r2);
        UNPK(lo, hi, a3); r2 = fmaf(-2.f, lo + hi, xx + __ldg(g_cc + kg + 3));
        v3 = __expf(-__ldg(g_s2 + kg + 3) * r2);
        psum += (v0 + v1) + (v2 + v3);

        __nv_bfloat16 h0 = __float2bfloat16(v0), h1 = __float2bfloat16(v1);
        __nv_bfloat16 h2 = __float2bfloat16(v2), h3 = __float2bfloat16(v3);
        __nv_bfloat16 l0 = __float2bfloat16(v0 - __bfloat162float(h0));
        __nv_bfloat16 l1 = __float2bfloat16(v1 - __bfloat162float(h1));
        __nv_bfloat16 l2 = __float2bfloat16(v2 - __bfloat162float(h2));
        __nv_bfloat16 l3 = __float2bfloat16(v3 - __bfloat162float(h3));
        const int kp = kg >> 1;
        A32[(kp    ) * AP + lane] = pack_bf2(h0, h1);
        A32[(kp + 1) * AP + lane] = pack_bf2(h2, h3);
        A32[(256 + kp    ) * AP + lane] = pack_bf2(l0, l1);
        A32[(256 + kp + 1) * AP + lane] = pack_bf2(l2, l3);
    }
    sm[SM_PART + warp * 32 + lane] = psum;
    __syncthreads();                       // sync #1: A tile + psum complete

    if (tid < 32) {
        float t = 1e-9f;
        #pragma unroll
        for (int w = 0; w < 16; w++) t += sm[SM_PART + w * 32 + tid];
        sm[SM_INV + tid] = 1.f / t;
    }
    __syncthreads();                       // sync #2: inv visible

    // ---- phase 3: M2xN8 warps, B via LDG register ring, zero syncs ----
    const int g   = lane >> 2;
    const int tig = lane & 3;
    const int wn  = warp & 7;              // 32-col group
    const int wm  = warp >> 3;             // 16-row half
    const int rofs = wm * 16;

    float acc[4][4];
    #pragma unroll
    for (int t = 0; t < 4; t++)
        #pragma unroll
        for (int i = 0; i < 4; i++) acc[t][i] = 0.f;

    const uint4* bsrc = (const uint4*)g_Wpk;
    uint4 bA[4], bB[4];
    #pragma unroll
    for (int i = 0; i < 4; i++) {
        int h = i >> 2, ks = i & 3;
        int ix = ((h * 8 + wn) * 4 + ks) * 64 + lane;
        bA[i] = __ldg(bsrc + ix);
        bB[i] = __ldg(bsrc + ix + 32);
    }

    // loop 1: chunks 0-7 (W_hi) — both R_hi and R_lo
    #pragma unroll 4
    for (int i = 0; i < 32; i++) {
        const int s  = i & 3;
        const int ks = i & 3;
        const int hk = i >> 2;
        const int kpA = hk * 32 + ks * 8 + tig;
        uint4 ba = bA[s], bb = bB[s];
        {   // prefetch i+4
            int nh = (i + 4) >> 2, nks = (i + 4) & 3;
            int ix = ((nh * 8 + wn) * 4 + nks) * 64 + lane;
            bA[s] = __ldg(bsrc + ix);
            bB[s] = __ldg(bsrc + ix + 32);
        }
        uint32_t h0 = A32[(kpA    ) * AP + g + rofs];
        uint32_t h1 = A32[(kpA    ) * AP + g + 8 + rofs];
        uint32_t h2 = A32[(kpA + 4) * AP + g + rofs];
        uint32_t h3 = A32[(kpA + 4) * AP + g + 8 + rofs];
        MMA16816(acc[0], h0, h1, h2, h3, ba.x, ba.y);
        MMA16816(acc[1], h0, h1, h2, h3, ba.z, ba.w);
        MMA16816(acc[2], h0, h1, h2, h3, bb.x, bb.y);
        MMA16816(acc[3], h0, h1, h2, h3, bb.z, bb.w);
        uint32_t l0 = A32[(kpA + 256) * AP + g + rofs];
        uint32_t l1 = A32[(kpA + 256) * AP + g + 8 + rofs];
        uint32_t l2 = A32[(kpA + 260) * AP + g + rofs];
        uint32_t l3 = A32[(kpA + 260) * AP + g + 8 + rofs];
        MMA16816(acc[0], l0, l1, l2, l3, ba.x, ba.y);
        MMA16816(acc[1], l0, l1, l2, l3, ba.z, ba.w);
        MMA16816(acc[2], l0, l1, l2, l3, bb.x, bb.y);
        MMA16816(acc[3], l0, l1, l2, l3, bb.z, bb.w);
    }
    // loop 2: chunks 8-15 (W_lo) — R_hi only
    #pragma unroll 4
    for (int i = 32; i < 64; i++) {
        const int s  = i & 3;
        const int ks = i & 3;
        const int hk = (i >> 2) & 7;
        const int kpA = hk * 32 + ks * 8 + tig;
        uint4 ba = bA[s], bb = bB[s];
        if (i + 4 < 64) {
            int nh = (i + 4) >> 2, nks = (i + 4) & 3;
            int ix = ((nh * 8 + wn) * 4 + nks) * 64 + lane;
            bA[s] = __ldg(bsrc + ix);
            bB[s] = __ldg(bsrc + ix + 32);
        }
        uint32_t h0 = A32[(kpA    ) * AP + g + rofs];
        uint32_t h1 = A32[(kpA    ) * AP + g + 8 + rofs];
        uint32_t h2 = A32[(kpA + 4) * AP + g + rofs];
        uint32_t h3 = A32[(kpA + 4) * AP + g + 8 + rofs];
        MMA16816(acc[0], h0, h1, h2, h3, ba.x, ba.y);
        MMA16816(acc[1], h0, h1, h2, h3, ba.z, ba.w);
        MMA16816(acc[2], h0, h1, h2, h3, bb.x, bb.y);
        MMA16816(acc[3], h0, h1, h2, h3, bb.z, bb.w);
    }

    // ---- epilogue: normalize + store ----
    const int r0 = rofs + g, r1 = r0 + 8;
    const float i0 = sm[SM_INV + r0];
    const float i1 = sm[SM_INV + r1];
    #pragma unroll
    for (int t = 0; t < 4; t++) {
        const int col = wn * 32 + t * 8 + tig * 2;
        *(float2*)(out + (size_t)(b0 + r0) * FOUT + col) =
            make_float2(acc[t][0] * i0, acc[t][1] * i0);
        *(float2*)(out + (size_t)(b0 + r1) * FOUT + col) =
            make_float2(acc[t][2] * i1, acc[t][3] * i1);
    }
}

// -------- launch --------
extern "C" void kernel_launch(void* const* d_in, const int* in_sizes, int n_in,
                              void* d_out, int out_size) {
    const float* x       = (const float*)d_in[0];  // [4096, 64]
    const float* W       = (const float*)d_in[1];  // [256, 512]
    const float* centers = (const float*)d_in[2];  // [512, 64]
    const float* ls      = (const float*)d_in[3];  // [512]
    float* out = (float*)d_out;                    // [4096, 256]

    cudaFuncSetAttribute(rbf_main, cudaFuncAttributeMaxDynamicSharedMemorySize, SMEM_BYTES);

    prep_all<<<16 + 512, 256>>>(W, centers, ls);
    rbf_main<<<B_ / TB, NTHR, SMEM_BYTES>>>(x, centers, out);
}

// round 9
// speedup vs baseline: 1.6042x; 1.6042x over previous
#include <cuda_runtime.h>
#include <cuda_bf16.h>
#include <cstdint>

#define B_    4096
#define FIN   64
#define NK    512
#define FOUT  256
#define TB    32
#define NTHR  512
#define AP    40            // A pitch in b32: conflict-free fragment access

typedef unsigned long long ull;

__device__ float    g_cc[NK];
__device__ float    g_s2[NK];
__device__ uint32_t g_Wpk[131072];   // 512KB: phase-3 B fragments, register order (R8 layout)
__device__ uint4    g_Cpk[8192];     // 128KB: phase-1 B fragments (centers split-bf16)
                                     // idx = ((w*8 + phys)*2 + tp)*32 + lane
                                     // phys 0-3 = C_hi(ks), 4-7 = C_lo(ks)

// ---- smem (u32 offsets) ----
#define SM_A    0               // [512 kp_eff][AP]: kp 0-255 = R_hi, 256-511 = R_lo
#define SM_PART 20480           // [16][32]
#define SM_INV  20992
#define SM_XX   21024
#define SM_CC   21056
#define SM_S2   21568
#define SM_TOT  22080
#define SMEM_BYTES (SM_TOT * 4) // ~88 KB

__device__ __forceinline__ uint32_t pack_bf2(__nv_bfloat16 a, __nv_bfloat16 b) {
    __nv_bfloat162 t; t.x = a; t.y = b;
    return *reinterpret_cast<uint32_t*>(&t);
}
__device__ __forceinline__ uint32_t split_hi(float a, float b) {
    return pack_bf2(__float2bfloat16(a), __float2bfloat16(b));
}
__device__ __forceinline__ uint32_t split_lo(float a, float b) {
    __nv_bfloat16 ha = __float2bfloat16(a), hb = __float2bfloat16(b);
    return pack_bf2(__float2bfloat16(a - __bfloat162float(ha)),
                    __float2bfloat16(b - __bfloat162float(hb)));
}

#define MMA16816(D,a0,a1,a2,a3,b0,b1) \
    asm("mma.sync.aligned.m16n8k16.row.col.f32.bf16.bf16.f32 " \
        "{%0,%1,%2,%3}, {%4,%5,%6,%7}, {%8,%9}, {%0,%1,%2,%3};" \
        : "+f"(D[0]), "+f"(D[1]), "+f"(D[2]), "+f"(D[3]) \
        : "r"(a0), "r"(a1), "r"(a2), "r"(a3), "r"(b0), "r"(b1))

// -------- prep: stats, W pack (register order), centers pack --------
__global__ void prep_all(const float* __restrict__ W,
                         const float* __restrict__ centers,
                         const float* __restrict__ ls) {
    int bid = blockIdx.x;
    if (bid < 16) {
        int kb = bid * 32;
        int warp = threadIdx.x >> 5, lane = threadIdx.x & 31;
        #pragma unroll
        for (int c = warp; c < 32; c += 8) {
            int k = kb + c;
            float v0 = centers[k * FIN + lane];
            float v1 = centers[k * FIN + 32 + lane];
            float s = fmaf(v0, v0, v1 * v1);
            #pragma unroll
            for (int off = 16; off; off >>= 1) s += __shfl_xor_sync(0xffffffffu, s, off);
            if (lane == 0) g_cc[k] = s;
        }
        if (threadIdx.x < 32) g_s2[kb + threadIdx.x] = __expf(2.f * ls[kb + threadIdx.x]);
    } else if (bid < 528) {
        // phase-3 W pack (same as R8)
        int q = (bid - 16) * 256 + threadIdx.x;
        int jp   = q & 3;
        int lane = (q >> 2) & 31;
        int half = (q >> 7) & 1;
        int ks   = (q >> 8) & 3;
        int wn   = (q >> 10) & 7;
        int h    = q >> 13;
        int j    = half * 4 + jp;
        int t    = j >> 1;
        int ki   = j & 1;
        int g    = lane >> 2;
        int tig  = lane & 3;
        int col  = wn * 32 + t * 8 + g;
        int k    = (h & 7) * 64 + (ks * 8 + tig) * 2 + 8 * ki;
        float w0 = W[(size_t)col * NK + k];
        float w1 = W[(size_t)col * NK + k + 1];
        g_Wpk[q] = (h >= 8) ? split_lo(w0, w1) : split_hi(w0, w1);
    } else {
        // phase-1 centers pack: uint4 per thread
        int q = (bid - 528) * 256 + threadIdx.x;   // 0..8191
        int lane = q & 31;
        int tp   = (q >> 5) & 1;
        int phys = (q >> 6) & 7;
        int w    = q >> 9;
        int g    = lane >> 2;
        int tig  = lane & 3;
        int ks   = phys & 3;
        bool lo  = phys >= 4;
        int colA = w * 32 + (2 * tp) * 8 + g;
        int colB = colA + 8;
        int k0   = 16 * ks + 2 * tig;
        int k1   = k0 + 8;
        const float* cA = centers + (size_t)colA * FIN;
        const float* cB = centers + (size_t)colB * FIN;
        float2 a0 = *(const float2*)(cA + k0);
        float2 a1 = *(const float2*)(cA + k1);
        float2 b0 = *(const float2*)(cB + k0);
        float2 b1 = *(const float2*)(cB + k1);
        uint4 r;
        if (lo) {
            r.x = split_lo(a0.x, a0.y); r.y = split_lo(a1.x, a1.y);
            r.z = split_lo(b0.x, b0.y); r.w = split_lo(b1.x, b1.y);
        } else {
            r.x = split_hi(a0.x, a0.y); r.y = split_hi(a1.x, a1.y);
            r.z = split_hi(b0.x, b0.y); r.w = split_hi(b1.x, b1.y);
        }
        g_Cpk[q] = r;
    }
}

// -------- fused main kernel --------
__global__ __launch_bounds__(NTHR, 1)
void rbf_main(const float* __restrict__ x,
              float* __restrict__ out) {
    extern __shared__ float sm[];
    uint32_t* A32 = (uint32_t*)sm;
    const int tid  = threadIdx.x;
    const int lane = tid & 31;
    const int warp = tid >> 5;
    const int g    = lane >> 2;
    const int tig  = lane & 3;
    const int b0   = blockIdx.x * TB;

    // per-k constants into smem; warp 0 computes ||x||^2 per row
    sm[SM_CC + tid] = g_cc[tid];
    sm[SM_S2 + tid] = g_s2[tid];
    if (warp == 0) {
        const float4* xr4 = (const float4*)(x + (size_t)(b0 + lane) * FIN);
        float s = 0.f;
        #pragma unroll
        for (int f = 0; f < 16; f++) {
            float4 v = __ldg(xr4 + f);
            s = fmaf(v.x, v.x, s); s = fmaf(v.y, v.y, s);
            s = fmaf(v.z, v.z, s); s = fmaf(v.w, v.w, s);
        }
        sm[SM_XX + lane] = s;
    }

    // ---- phase 1: tensor GEMM dot = x @ C^T. D = xh*(ch+cl) + xl*ch ----
    // warp covers cols [32*warp, 32*warp+32), all 32 rows.
    float acc[2][4][4];
    #pragma unroll
    for (int m = 0; m < 2; m++)
        #pragma unroll
        for (int nt = 0; nt < 4; nt++)
            #pragma unroll
            for (int i = 0; i < 4; i++) acc[m][nt][i] = 0.f;

    const uint4* cp = g_Cpk + (size_t)warp * 512;   // (8 phys * 2 tp) * 32
    #pragma unroll
    for (int ks = 0; ks < 4; ks++) {
        uint4 bh0 = __ldg(cp + (ks * 2 + 0) * 32 + lane);        // C_hi, nt 0,1
        uint4 bh1 = __ldg(cp + (ks * 2 + 1) * 32 + lane);        // C_hi, nt 2,3
        uint4 bl0 = __ldg(cp + ((4 + ks) * 2 + 0) * 32 + lane);  // C_lo, nt 0,1
        uint4 bl1 = __ldg(cp + ((4 + ks) * 2 + 1) * 32 + lane);  // C_lo, nt 2,3
        #pragma unroll
        for (int m = 0; m < 2; m++) {
            const float* xb = x + (size_t)(b0 + g + 16 * m) * FIN + 16 * ks + 2 * tig;
            float2 v0 = __ldg((const float2*)xb);
            float2 v1 = __ldg((const float2*)(xb + 8 * FIN));
            float2 v2 = __ldg((const float2*)(xb + 8));
            float2 v3 = __ldg((const float2*)(xb + 8 * FIN + 8));
            uint32_t ah0 = split_hi(v0.x, v0.y), ah1 = split_hi(v1.x, v1.y);
            uint32_t ah2 = split_hi(v2.x, v2.y), ah3 = split_hi(v3.x, v3.y);
            uint32_t al0 = split_lo(v0.x, v0.y), al1 = split_lo(v1.x, v1.y);
            uint32_t al2 = split_lo(v2.x, v2.y), al3 = split_lo(v3.x, v3.y);
            MMA16816(acc[m][0], ah0, ah1, ah2, ah3, bh0.x, bh0.y);
            MMA16816(acc[m][1], ah0, ah1, ah2, ah3, bh0.z, bh0.w);
            MMA16816(acc[m][2], ah0, ah1, ah2, ah3, bh1.x, bh1.y);
            MMA16816(acc[m][3], ah0, ah1, ah2, ah3, bh1.z, bh1.w);
            MMA16816(acc[m][0], ah0, ah1, ah2, ah3, bl0.x, bl0.y);
            MMA16816(acc[m][1], ah0, ah1, ah2, ah3, bl0.z, bl0.w);
            MMA16816(acc[m][2], ah0, ah1, ah2, ah3, bl1.x, bl1.y);
            MMA16816(acc[m][3], ah0, ah1, ah2, ah3, bl1.z, bl1.w);
            MMA16816(acc[m][0], al0, al1, al2, al3, bh0.x, bh0.y);
            MMA16816(acc[m][1], al0, al1, al2, al3, bh0.z, bh0.w);
            MMA16816(acc[m][2], al0, al1, al2, al3, bh1.x, bh1.y);
            MMA16816(acc[m][3], al0, al1, al2, al3, bh1.z, bh1.w);
        }
    }
    __syncthreads();    // xx/cc/s2 visible; A32 region free to write

    // ---- epilogue: r2 -> exp -> split-bf16 A-tile + row partial sums ----
    float psumr[4] = {0.f, 0.f, 0.f, 0.f};
    #pragma unroll
    for (int m = 0; m < 2; m++) {
        const int row0 = g + 16 * m;
        const int row1 = row0 + 8;
        const float xx0 = sm[SM_XX + row0];
        const float xx1 = sm[SM_XX + row1];
        #pragma unroll
        for (int nt = 0; nt < 4; nt++) {
            const int colp = warp * 32 + nt * 8 + 2 * tig;
            const int kp   = colp >> 1;
            const float cc0 = sm[SM_CC + colp], cc1 = sm[SM_CC + colp + 1];
            const float s20 = sm[SM_S2 + colp], s21 = sm[SM_S2 + colp + 1];
            float r2, v00, v01, v10, v11;
            r2 = fmaf(-2.f, acc[m][nt][0], xx0 + cc0); v00 = __expf(-s20 * r2);
            r2 = fmaf(-2.f, acc[m][nt][1], xx0 + cc1); v01 = __expf(-s21 * r2);
            r2 = fmaf(-2.f, acc[m][nt][2], xx1 + cc0); v10 = __expf(-s20 * r2);
            r2 = fmaf(-2.f, acc[m][nt][3], xx1 + cc1); v11 = __expf(-s21 * r2);
            psumr[m * 2 + 0] += v00 + v01;
            psumr[m * 2 + 1] += v10 + v11;
            A32[(kp      ) * AP + row0] = split_hi(v00, v01);
            A32[(kp      ) * AP + row1] = split_hi(v10, v11);
            A32[(kp + 256) * AP + row0] = split_lo(v00, v01);
            A32[(kp + 256) * AP + row1] = split_lo(v10, v11);
        }
    }
    // reduce partial sums over tig (4 lanes share the same rows)
    #pragma unroll
    for (int i = 0; i < 4; i++) {
        psumr[i] += __shfl_xor_sync(0xffffffffu, psumr[i], 1);
        psumr[i] += __shfl_xor_sync(0xffffffffu, psumr[i], 2);
    }
    if (tig == 0) {
        sm[SM_PART + warp * 32 + g     ] = psumr[0];
        sm[SM_PART + warp * 32 + g + 8 ] = psumr[1];
        sm[SM_PART + warp * 32 + g + 16] = psumr[2];
        sm[SM_PART + warp * 32 + g + 24] = psumr[3];
    }
    __syncthreads();

    if (tid < 32) {
        float t = 1e-9f;
        #pragma unroll
        for (int w = 0; w < 16; w++) t += sm[SM_PART + w * 32 + tid];
        sm[SM_INV + tid] = 1.f / t;
    }
    __syncthreads();

    // ---- phase 3: M2xN8 warps, B via LDG register ring (R8, verified) ----
    const int wn  = warp & 7;
    const int wm  = warp >> 3;
    const int rofs = wm * 16;

    float pacc[4][4];
    #pragma unroll
    for (int t = 0; t < 4; t++)
        #pragma unroll
        for (int i = 0; i < 4; i++) pacc[t][i] = 0.f;

    const uint4* bsrc = (const uint4*)g_Wpk;
    uint4 bA[4], bB[4];
    #pragma unroll
    for (int i = 0; i < 4; i++) {
        int h = i >> 2, ks = i & 3;
        int ix = ((h * 8 + wn) * 4 + ks) * 64 + lane;
        bA[i] = __ldg(bsrc + ix);
        bB[i] = __ldg(bsrc + ix + 32);
    }

    // loop 1: chunks 0-7 (W_hi) — R_hi and R_lo
    #pragma unroll 4
    for (int i = 0; i < 32; i++) {
        const int s  = i & 3;
        const int ks = i & 3;
        const int hk = i >> 2;
        const int kpA = hk * 32 + ks * 8 + tig;
        uint4 ba = bA[s], bb = bB[s];
        {
            int nh = (i + 4) >> 2, nks = (i + 4) & 3;
            int ix = ((nh * 8 + wn) * 4 + nks) * 64 + lane;
            bA[s] = __ldg(bsrc + ix);
            bB[s] = __ldg(bsrc + ix + 32);
        }
        uint32_t h0 = A32[(kpA    ) * AP + g + rofs];
        uint32_t h1 = A32[(kpA    ) * AP + g + 8 + rofs];
        uint32_t h2 = A32[(kpA + 4) * AP + g + rofs];
        uint32_t h3 = A32[(kpA + 4) * AP + g + 8 + rofs];
        MMA16816(pacc[0], h0, h1, h2, h3, ba.x, ba.y);
        MMA16816(pacc[1], h0, h1, h2, h3, ba.z, ba.w);
        MMA16816(pacc[2], h0, h1, h2, h3, bb.x, bb.y);
        MMA16816(pacc[3], h0, h1, h2, h3, bb.z, bb.w);
        uint32_t l0 = A32[(kpA + 256) * AP + g + rofs];
        uint32_t l1 = A32[(kpA + 256) * AP + g + 8 + rofs];
        uint32_t l2 = A32[(kpA + 260) * AP + g + rofs];
        uint32_t l3 = A32[(kpA + 260) * AP + g + 8 + rofs];
        MMA16816(pacc[0], l0, l1, l2, l3, ba.x, ba.y);
        MMA16816(pacc[1], l0, l1, l2, l3, ba.z, ba.w);
        MMA16816(pacc[2], l0, l1, l2, l3, bb.x, bb.y);
        MMA16816(pacc[3], l0, l1, l2, l3, bb.z, bb.w);
    }
    // loop 2: chunks 8-15 (W_lo) — R_hi only
    #pragma unroll 4
    for (int i = 32; i < 64; i++) {
        const int s  = i & 3;
        const int ks = i & 3;
        const int hk = (i >> 2) & 7;
        const int kpA = hk * 32 + ks * 8 + tig;
        uint4 ba = bA[s], bb = bB[s];
        if (i + 4 < 64) {
            int nh = (i + 4) >> 2, nks = (i + 4) & 3;
            int ix = ((nh * 8 + wn) * 4 + nks) * 64 + lane;
            bA[s] = __ldg(bsrc + ix);
            bB[s] = __ldg(bsrc + ix + 32);
        }
        uint32_t h0 = A32[(kpA    ) * AP + g + rofs];
        uint32_t h1 = A32[(kpA    ) * AP + g + 8 + rofs];
        uint32_t h2 = A32[(kpA + 4) * AP + g + rofs];
        uint32_t h3 = A32[(kpA + 4) * AP + g + 8 + rofs];
        MMA16816(pacc[0], h0, h1, h2, h3, ba.x, ba.y);
        MMA16816(pacc[1], h0, h1, h2, h3, ba.z, ba.w);
        MMA16816(pacc[2], h0, h1, h2, h3, bb.x, bb.y);
        MMA16816(pacc[3], h0, h1, h2, h3, bb.z, bb.w);
    }

    // ---- epilogue: normalize + store ----
    const int r0 = rofs + g, r1 = r0 + 8;
    const float i0 = sm[SM_INV + r0];
    const float i1 = sm[SM_INV + r1];
    #pragma unroll
    for (int t = 0; t < 4; t++) {
        const int col = wn * 32 + t * 8 + tig * 2;
        *(float2*)(out + (size_t)(b0 + r0) * FOUT + col) =
            make_float2(pacc[t][0] * i0, pacc[t][1] * i0);
        *(float2*)(out + (size_t)(b0 + r1) * FOUT + col) =
            make_float2(pacc[t][2] * i1, pacc[t][3] * i1);
    }
}

// -------- launch --------
extern "C" void kernel_launch(void* const* d_in, const int* in_sizes, int n_in,
                              void* d_out, int out_size) {
    const float* x       = (const float*)d_in[0];  // [4096, 64]
    const float* W       = (const float*)d_in[1];  // [256, 512]
    const float* centers = (const float*)d_in[2];  // [512, 64]
    const float* ls      = (const float*)d_in[3];  // [512]
    float* out = (float*)d_out;                    // [4096, 256]

    cudaFuncSetAttribute(rbf_main, cudaFuncAttributeMaxDynamicSharedMemorySize, SMEM_BYTES);

    prep_all<<<16 + 512 + 32, 256>>>(W, centers, ls);
    rbf_main<<<B_ / TB, NTHR, SMEM_BYTES>>>(x, out);
}

// round 10
// speedup vs baseline: 1.7135x; 1.0682x over previous
#include <cuda_runtime.h>
#include <cuda_bf16.h>
#include <cstdint>

#define B_    4096
#define FIN   64
#define NK    512
#define FOUT  256
#define TB    32
#define NTHR  512
#define AP    40            // A pitch in b32: conflict-free fragment access
#define XRP   68            // staged x pitch (floats)

typedef unsigned long long ull;

__device__ float    g_cc[NK];
__device__ float    g_s2[NK];
__device__ uint32_t g_Wpk[131072];   // 512KB: phase-3 B fragments, register order
__device__ uint4    g_Cpk[8192];     // 128KB: phase-1 B fragments (centers split-bf16)

// ---- smem (u32 offsets) ----
#define SM_A    0               // [512 kp_eff][AP]: kp 0-255 = R_hi, 256-511 = R_lo
#define SM_XR   20480           // staged x [32][XRP] floats
#define SM_XF   22656           // x fragments: 16 frags x 32 lanes x uint4
#define SM_PART 24704           // [16][32]
#define SM_INV  25216
#define SM_XX   25248
#define SM_CC   25280
#define SM_S2   25792
#define SM_TOT  26304
#define SMEM_BYTES (SM_TOT * 4) // ~105 KB

__device__ __forceinline__ uint32_t pack_bf2(__nv_bfloat16 a, __nv_bfloat16 b) {
    __nv_bfloat162 t; t.x = a; t.y = b;
    return *reinterpret_cast<uint32_t*>(&t);
}
__device__ __forceinline__ uint32_t split_hi(float a, float b) {
    return pack_bf2(__float2bfloat16(a), __float2bfloat16(b));
}
__device__ __forceinline__ uint32_t split_lo(float a, float b) {
    __nv_bfloat16 ha = __float2bfloat16(a), hb = __float2bfloat16(b);
    return pack_bf2(__float2bfloat16(a - __bfloat162float(ha)),
                    __float2bfloat16(b - __bfloat162float(hb)));
}

#define MMA16816(D,a0,a1,a2,a3,b0,b1) \
    asm("mma.sync.aligned.m16n8k16.row.col.f32.bf16.bf16.f32 " \
        "{%0,%1,%2,%3}, {%4,%5,%6,%7}, {%8,%9}, {%0,%1,%2,%3};" \
        : "+f"(D[0]), "+f"(D[1]), "+f"(D[2]), "+f"(D[3]) \
        : "r"(a0), "r"(a1), "r"(a2), "r"(a3), "r"(b0), "r"(b1))

// -------- prep: stats, W pack (coalesced reads), centers pack --------
__global__ void prep_all(const float* __restrict__ W,
                         const float* __restrict__ centers,
                         const float* __restrict__ ls) {
    int bid = blockIdx.x;
    if (bid < 16) {
        int kb = bid * 32;
        int warp = threadIdx.x >> 5, lane = threadIdx.x & 31;
        #pragma unroll
        for (int c = warp; c < 32; c += 8) {
            int k = kb + c;
            float v0 = centers[k * FIN + lane];
            float v1 = centers[k * FIN + 32 + lane];
            float s = fmaf(v0, v0, v1 * v1);
            #pragma unroll
            for (int off = 16; off; off >>= 1) s += __shfl_xor_sync(0xffffffffu, s, off);
            if (lane == 0) g_cc[k] = s;
        }
        if (threadIdx.x < 32) g_s2[kb + threadIdx.x] = __expf(2.f * ls[kb + threadIdx.x]);
    } else if (bid < 528) {
        // W pack, coalesced reads: thread <- (split, col, kpair)
        int q = (bid - 16) * 256 + threadIdx.x;   // 0..131071
        int split = q >> 16;                      // 0 = hi, 1 = lo
        int rem   = q & 65535;
        int col   = rem >> 8;                     // 0..255
        int kp2   = rem & 255;                    // k-pair, consecutive per lane
        float2 wv = *(const float2*)(W + (size_t)col * NK + 2 * kp2);
        int h   = split * 8 + (kp2 >> 5);
        int kl  = kp2 & 31;
        int tig = kl & 3, ki = (kl >> 2) & 1, ks = kl >> 3;
        int g   = col & 7, t = (col >> 3) & 3, wn = col >> 5;
        int j   = 2 * t + ki, half = j >> 2, jp = j & 3;
        int lane = g * 4 + tig;
        int qo = jp | (lane << 2) | (half << 7) | (ks << 8) | (wn << 10) | (h << 13);
        g_Wpk[qo] = split ? split_lo(wv.x, wv.y) : split_hi(wv.x, wv.y);
    } else {
        // phase-1 centers pack (verified R9 layout)
        int q = (bid - 528) * 256 + threadIdx.x;   // 0..8191
        int lane = q & 31;
        int tp   = (q >> 5) & 1;
        int phys = (q >> 6) & 7;
        int w    = q >> 9;
        int g    = lane >> 2;
        int tig  = lane & 3;
        int ks   = phys & 3;
        bool lo  = phys >= 4;
        int colA = w * 32 + (2 * tp) * 8 + g;
        int colB = colA + 8;
        int k0   = 16 * ks + 2 * tig;
        int k1   = k0 + 8;
        const float* cA = centers + (size_t)colA * FIN;
        const float* cB = centers + (size_t)colB * FIN;
        float2 a0 = *(const float2*)(cA + k0);
        float2 a1 = *(const float2*)(cA + k1);
        float2 b0 = *(const float2*)(cB + k0);
        float2 b1 = *(const float2*)(cB + k1);
        uint4 r;
        if (lo) {
            r.x = split_lo(a0.x, a0.y); r.y = split_lo(a1.x, a1.y);
            r.z = split_lo(b0.x, b0.y); r.w = split_lo(b1.x, b1.y);
        } else {
            r.x = split_hi(a0.x, a0.y); r.y = split_hi(a1.x, a1.y);
            r.z = split_hi(b0.x, b0.y); r.w = split_hi(b1.x, b1.y);
        }
        g_Cpk[q] = r;
    }
}

// -------- fused main kernel --------
__global__ __launch_bounds__(NTHR, 1)
void rbf_main(const float* __restrict__ x,
              float* __restrict__ out) {
    extern __shared__ float sm[];
    uint32_t* A32 = (uint32_t*)sm;
    const int tid  = threadIdx.x;
    const int lane = tid & 31;
    const int warp = tid >> 5;
    const int g    = lane >> 2;
    const int tig  = lane & 3;
    const int b0   = blockIdx.x * TB;

    // ---- stage 1: coalesced x tile load + per-k constants ----
    sm[SM_CC + tid] = g_cc[tid];
    sm[SM_S2 + tid] = g_s2[tid];
    {
        const float4* x4 = (const float4*)(x + (size_t)b0 * FIN);
        int r = tid >> 4, c = tid & 15;
        *(float4*)&sm[SM_XR + r * XRP + c * 4] = __ldg(x4 + tid);
    }
    __syncthreads();

    // ---- stage 2a: ||x||^2 (warp w handles rows 2w, 2w+1) ----
    {
        int row = 2 * warp + (lane >> 4);
        float4 v = *(const float4*)&sm[SM_XR + row * XRP + (lane & 15) * 4];
        float s = fmaf(v.x, v.x, v.y * v.y) + fmaf(v.z, v.z, v.w * v.w);
        s += __shfl_xor_sync(0xffffffffu, s, 1);
        s += __shfl_xor_sync(0xffffffffu, s, 2);
        s += __shfl_xor_sync(0xffffffffu, s, 4);
        s += __shfl_xor_sync(0xffffffffu, s, 8);
        if ((lane & 15) == 0) sm[SM_XX + row] = s;
    }
    // ---- stage 2b: build shared x fragments (tid -> one uint4) ----
    {
        int fid = tid >> 5;                   // m = fid>>3, ks = (fid>>1)&3, sp = fid&1
        int gg  = (tid >> 2) & 7;
        int tt  = tid & 3;
        int m   = fid >> 3, ks = (fid >> 1) & 3, sp = fid & 1;
        int row0 = gg + 16 * m;
        int col0 = 16 * ks + 2 * tt;
        float2 u0 = *(const float2*)&sm[SM_XR + row0 * XRP + col0];
        float2 u1 = *(const float2*)&sm[SM_XR + (row0 + 8) * XRP + col0];
        float2 u2 = *(const float2*)&sm[SM_XR + row0 * XRP + col0 + 8];
        float2 u3 = *(const float2*)&sm[SM_XR + (row0 + 8) * XRP + col0 + 8];
        uint4 fr;
        if (sp) {
            fr.x = split_lo(u0.x, u0.y); fr.y = split_lo(u1.x, u1.y);
            fr.z = split_lo(u2.x, u2.y); fr.w = split_lo(u3.x, u3.y);
        } else {
            fr.x = split_hi(u0.x, u0.y); fr.y = split_hi(u1.x, u1.y);
            fr.z = split_hi(u2.x, u2.y); fr.w = split_hi(u3.x, u3.y);
        }
        ((uint4*)((uint32_t*)sm + SM_XF))[tid] = fr;
    }
    __syncthreads();

    // ---- phase 1: tensor GEMM dot = x @ C^T; D = xh*(ch+cl) + xl*ch ----
    float acc[2][4][4];
    #pragma unroll
    for (int m = 0; m < 2; m++)
        #pragma unroll
        for (int nt = 0; nt < 4; nt++)
            #pragma unroll
            for (int i = 0; i < 4; i++) acc[m][nt][i] = 0.f;

    const uint4* cp  = g_Cpk + (size_t)warp * 512;
    const uint4* XFv = (const uint4*)((uint32_t*)sm + SM_XF);
    #pragma unroll
    for (int ks = 0; ks < 4; ks++) {
        uint4 bh0 = __ldg(cp + (ks * 2 + 0) * 32 + lane);
        uint4 bh1 = __ldg(cp + (ks * 2 + 1) * 32 + lane);
        uint4 bl0 = __ldg(cp + ((4 + ks) * 2 + 0) * 32 + lane);
        uint4 bl1 = __ldg(cp + ((4 + ks) * 2 + 1) * 32 + lane);
        #pragma unroll
        for (int m = 0; m < 2; m++) {
            uint4 ah = XFv[((m * 4 + ks) * 2 + 0) * 32 + lane];
            uint4 al = XFv[((m * 4 + ks) * 2 + 1) * 32 + lane];
            MMA16816(acc[m][0], ah.x, ah.y, ah.z, ah.w, bh0.x, bh0.y);
            MMA16816(acc[m][1], ah.x, ah.y, ah.z, ah.w, bh0.z, bh0.w);
            MMA16816(acc[m][2], ah.x, ah.y, ah.z, ah.w, bh1.x, bh1.y);
            MMA16816(acc[m][3], ah.x, ah.y, ah.z, ah.w, bh1.z, bh1.w);
            MMA16816(acc[m][0], ah.x, ah.y, ah.z, ah.w, bl0.x, bl0.y);
            MMA16816(acc[m][1], ah.x, ah.y, ah.z, ah.w, bl0.z, bl0.w);
            MMA16816(acc[m][2], ah.x, ah.y, ah.z, ah.w, bl1.x, bl1.y);
            MMA16816(acc[m][3], ah.x, ah.y, ah.z, ah.w, bl1.z, bl1.w);
            MMA16816(acc[m][0], al.x, al.y, al.z, al.w, bh0.x, bh0.y);
            MMA16816(acc[m][1], al.x, al.y, al.z, al.w, bh0.z, bh0.w);
            MMA16816(acc[m][2], al.x, al.y, al.z, al.w, bh1.x, bh1.y);
            MMA16816(acc[m][3], al.x, al.y, al.z, al.w, bh1.z, bh1.w);
        }
    }

    // ---- phase-1 epilogue: r2 -> exp -> split-bf16 A-tile + row partial sums ----
    float psumr[4] = {0.f, 0.f, 0.f, 0.f};
    #pragma unroll
    for (int m = 0; m < 2; m++) {
        const int row0 = g + 16 * m;
        const int row1 = row0 + 8;
        const float xx0 = sm[SM_XX + row0];
        const float xx1 = sm[SM_XX + row1];
        #pragma unroll
        for (int nt = 0; nt < 4; nt++) {
            const int colp = warp * 32 + nt * 8 + 2 * tig;
            const int kp   = colp >> 1;
            const float cc0 = sm[SM_CC + colp], cc1 = sm[SM_CC + colp + 1];
            const float s20 = sm[SM_S2 + colp], s21 = sm[SM_S2 + colp + 1];
            float r2, v00, v01, v10, v11;
            r2 = fmaf(-2.f, acc[m][nt][0], xx0 + cc0); v00 = __expf(-s20 * r2);
            r2 = fmaf(-2.f, acc[m][nt][1], xx0 + cc1); v01 = __expf(-s21 * r2);
            r2 = fmaf(-2.f, acc[m][nt][2], xx1 + cc0); v10 = __expf(-s20 * r2);
            r2 = fmaf(-2.f, acc[m][nt][3], xx1 + cc1); v11 = __expf(-s21 * r2);
            psumr[m * 2 + 0] += v00 + v01;
            psumr[m * 2 + 1] += v10 + v11;
            A32[(kp      ) * AP + row0] = split_hi(v00, v01);
            A32[(kp      ) * AP + row1] = split_hi(v10, v11);
            A32[(kp + 256) * AP + row0] = split_lo(v00, v01);
            A32[(kp + 256) * AP + row1] = split_lo(v10, v11);
        }
    }
    #pragma unroll
    for (int i = 0; i < 4; i++) {
        psumr[i] += __shfl_xor_sync(0xffffffffu, psumr[i], 1);
        psumr[i] += __shfl_xor_sync(0xffffffffu, psumr[i], 2);
    }
    if (tig == 0) {
        sm[SM_PART + warp * 32 + g     ] = psumr[0];
        sm[SM_PART + warp * 32 + g + 8 ] = psumr[1];
        sm[SM_PART + warp * 32 + g + 16] = psumr[2];
        sm[SM_PART + warp * 32 + g + 24] = psumr[3];
    }
    __syncthreads();

    if (tid < 32) {
        float t = 1e-9f;
        #pragma unroll
        for (int w = 0; w < 16; w++) t += sm[SM_PART + w * 32 + tid];
        sm[SM_INV + tid] = 1.f / t;
    }
    __syncthreads();

    // ---- phase 3: M2xN8 warps, B via LDG register ring, fully unrolled ----
    const int wn  = warp & 7;
    const int wm  = warp >> 3;
    const int rofs = wm * 16;

    float pacc[4][4];
    #pragma unroll
    for (int t = 0; t < 4; t++)
        #pragma unroll
        for (int i = 0; i < 4; i++) pacc[t][i] = 0.f;

    const uint4* bsrc = (const uint4*)g_Wpk;
    const uint32_t* Ab = A32 + g + rofs;
    uint4 bA[4], bB[4];
    #pragma unroll
    for (int i = 0; i < 4; i++) {
        int ix = ((0 * 8 + wn) * 4 + (i & 3)) * 64 + lane;
        bA[i] = __ldg(bsrc + ix);
        bB[i] = __ldg(bsrc + ix + 32);
    }

    // loop 1: chunks 0-7 (W_hi) - R_hi and R_lo
    #pragma unroll
    for (int i = 0; i < 32; i++) {
        const int s  = i & 3;
        const int ks = i & 3;
        const int hk = i >> 2;
        const int kpA = hk * 32 + ks * 8 + tig;
        uint4 ba = bA[s], bb = bB[s];
        {
            const int nh = (i + 4) >> 2, nks = (i + 4) & 3;
            const int ix = ((nh * 8 + wn) * 4 + nks) * 64 + lane;
            bA[s] = __ldg(bsrc + ix);
            bB[s] = __ldg(bsrc + ix + 32);
        }
        uint32_t h0 = Ab[(kpA    ) * AP];
        uint32_t h1 = Ab[(kpA    ) * AP + 8];
        uint32_t h2 = Ab[(kpA + 4) * AP];
        uint32_t h3 = Ab[(kpA + 4) * AP + 8];
        MMA16816(pacc[0], h0, h1, h2, h3, ba.x, ba.y);
        MMA16816(pacc[1], h0, h1, h2, h3, ba.z, ba.w);
        MMA16816(pacc[2], h0, h1, h2, h3, bb.x, bb.y);
        MMA16816(pacc[3], h0, h1, h2, h3, bb.z, bb.w);
        uint32_t l0 = Ab[(kpA + 256) * AP];
        uint32_t l1 = Ab[(kpA + 256) * AP + 8];
        uint32_t l2 = Ab[(kpA + 260) * AP];
        uint32_t l3 = Ab[(kpA + 260) * AP + 8];
        MMA16816(pacc[0], l0, l1, l2, l3, ba.x, ba.y);
        MMA16816(pacc[1], l0, l1, l2, l3, ba.z, ba.w);
        MMA16816(pacc[2], l0, l1, l2, l3, bb.x, bb.y);
        MMA16816(pacc[3], l0, l1, l2, l3, bb.z, bb.w);
    }
    // loop 2: chunks 8-15 (W_lo) - R_hi only
    #pragma unroll
    for (int i = 32; i < 64; i++) {
        const int s  = i & 3;
        const int ks = i & 3;
        const int hk = (i >> 2) & 7;
        const int kpA = hk * 32 + ks * 8 + tig;
        uint4 ba = bA[s], bb = bB[s];
        if (i + 4 < 64) {
            const int nh = (i + 4) >> 2, nks = (i + 4) & 3;
            const int ix = ((nh * 8 + wn) * 4 + nks) * 64 + lane;
            bA[s] = __ldg(bsrc + ix);
            bB[s] = __ldg(bsrc + ix + 32);
        }
        uint32_t h0 = Ab[(kpA    ) * AP];
        uint32_t h1 = Ab[(kpA    ) * AP + 8];
        uint32_t h2 = Ab[(kpA + 4) * AP];
        uint32_t h3 = Ab[(kpA + 4) * AP + 8];
        MMA16816(pacc[0], h0, h1, h2, h3, ba.x, ba.y);
        MMA16816(pacc[1], h0, h1, h2, h3, ba.z, ba.w);
        MMA16816(pacc[2], h0, h1, h2, h3, bb.x, bb.y);
        MMA16816(pacc[3], h0, h1, h2, h3, bb.z, bb.w);
    }

    // ---- epilogue: normalize + store ----
    const int r0 = rofs + g, r1 = r0 + 8;
    const float i0 = sm[SM_INV + r0];
    const float i1 = sm[SM_INV + r1];
    #pragma unroll
    for (int t = 0; t < 4; t++) {
        const int col = wn * 32 + t * 8 + tig * 2;
        *(float2*)(out + (size_t)(b0 + r0) * FOUT + col) =
            make_float2(pacc[t][0] * i0, pacc[t][1] * i0);
        *(float2*)(out + (size_t)(b0 + r1) * FOUT + col) =
            make_float2(pacc[t][2] * i1, pacc[t][3] * i1);
    }
}

// -------- launch --------
extern "C" void kernel_launch(void* const* d_in, const int* in_sizes, int n_in,
                              void* d_out, int out_size) {
    const float* x       = (const float*)d_in[0];  // [4096, 64]
    const float* W       = (const float*)d_in[1];  // [256, 512]
    const float* centers = (const float*)d_in[2];  // [512, 64]
    const float* ls      = (const float*)d_in[3];  // [512]
    float* out = (float*)d_out;                    // [4096, 256]

    cudaFuncSetAttribute(rbf_main, cudaFuncAttributeMaxDynamicSharedMemorySize, SMEM_BYTES);

    prep_all<<<16 + 512 + 32, 256>>>(W, centers, ls);
    rbf_main<<<B_ / TB, NTHR, SMEM_BYTES>>>(x, out);
}